// round 1
// baseline (speedup 1.0000x reference)
#include <cuda_runtime.h>

namespace {
constexpr int H = 64, W = 64;
constexpr int C = 384;   // 48 positions * 8 channels
constexpr int B = 32;
constexpr int AP = 72;   // smem row pitch (floats), 288B -> 16B aligned rows
constexpr int AR = 68;   // logical rows/cols of padded+displaced tile
}

__global__ __launch_bounds__(256) void displace_gauss_kernel(
    const float* __restrict__ x, const float* __restrict__ offset,
    float* __restrict__ out) {
  __shared__ __align__(16) float A[AR * AP];
  __shared__ float swx[5], swy[5];
  __shared__ int soff[2];

  const int plane = blockIdx.x;         // b*C + c
  const int c = plane % C;
  const int p = c >> 3;                 // 8 channels per position
  const int tid = threadIdx.x;

  // --- per-block weight / integer-offset computation (cheap, broadcast) ---
  if (tid == 0) {
    float ox = offset[2 * p + 0];
    float oy = offset[2 * p + 1];
    float rx = rintf(ox), ry = rintf(oy);   // matches jnp.round (half-even)
    soff[0] = (int)rx;
    soff[1] = (int)ry;
    float subx = ox - rx, suby = oy - ry;
    float sx = 0.f, sy = 0.f;
#pragma unroll
    for (int j = 0; j < 5; j++) {
      float dj = (float)(j - 2) + subx;
      float di = (float)(j - 2) + suby;
      float ex = expf(-dj * dj * 2.0f);     // 1/(2*sigma^2) = 2, sigma=0.5
      float ey = expf(-di * di * 2.0f);
      swx[j] = ex; swy[j] = ey;
      sx += ex; sy += ey;
    }
    float isx = 1.f / sx, isy = 1.f / sy;   // 2D norm = prod of 1D norms
#pragma unroll
    for (int j = 0; j < 5; j++) { swx[j] *= isx; swy[j] *= isy; }
  }
  __syncthreads();

  const int dx = soff[0], dy = soff[1];
  const float* __restrict__ src = x + (size_t)plane * (H * W);

  // --- build displaced plane with 2-px zero halo; all masks applied here ---
  // A[Y][X] = disp_padded[Y-2][X-2]; disp[py][px] = x[py-dy][px-dx] (zero OOB)
  for (int idx = tid; idx < AR * AR; idx += 256) {
    int Y = idx / AR;
    int X = idx - Y * AR;
    int py = Y - 2, px = X - 2;
    int sy = py - dy, sx2 = px - dx;
    float v = 0.f;
    if ((unsigned)py < (unsigned)H && (unsigned)px < (unsigned)W &&
        (unsigned)sy < (unsigned)H && (unsigned)sx2 < (unsigned)W)
      v = src[sy * W + sx2];
    A[Y * AP + X] = v;
  }
  __syncthreads();

  const float wx0 = swx[0], wx1 = swx[1], wx2 = swx[2], wx3 = swx[3], wx4 = swx[4];
  float wy[5];
#pragma unroll
  for (int i = 0; i < 5; i++) wy[i] = swy[i];

  // --- separable conv, 4x4 outputs per thread, register row-sliding ---
  const int txi = tid & 15;      // 16 x-tiles of width 4
  const int tyi = tid >> 4;      // 16 y-tiles of height 4
  const int x0 = txi * 4;
  const int y0 = tyi * 4;

  float acc[4][4];
#pragma unroll
  for (int o = 0; o < 4; o++)
#pragma unroll
    for (int u = 0; u < 4; u++) acc[o][u] = 0.f;

#pragma unroll
  for (int r = 0; r < 8; r++) {           // 8 h-rows feed 4 output rows
    const float* row = &A[(y0 + r) * AP + x0];
    float4 a0 = *reinterpret_cast<const float4*>(row);
    float4 a1 = *reinterpret_cast<const float4*>(row + 4);
    float a[8] = {a0.x, a0.y, a0.z, a0.w, a1.x, a1.y, a1.z, a1.w};
    float h[4];
#pragma unroll
    for (int u = 0; u < 4; u++)
      h[u] = wx0 * a[u] + wx1 * a[u + 1] + wx2 * a[u + 2]
           + wx3 * a[u + 3] + wx4 * a[u + 4];
#pragma unroll
    for (int o = 0; o < 4; o++) {
      int i = r - o;                      // compile-time pruned
      if (i >= 0 && i < 5) {
        float wv = wy[i];
#pragma unroll
        for (int u = 0; u < 4; u++) acc[o][u] += wv * h[u];
      }
    }
  }

  float* __restrict__ dst = out + (size_t)plane * (H * W);
#pragma unroll
  for (int o = 0; o < 4; o++) {
    float4 v = make_float4(acc[o][0], acc[o][1], acc[o][2], acc[o][3]);
    *reinterpret_cast<float4*>(&dst[(y0 + o) * W + x0]) = v;
  }
}

extern "C" void kernel_launch(void* const* d_in, const int* in_sizes, int n_in,
                              void* d_out, int out_size) {
  const float* x = (const float*)d_in[0];
  const float* offset = (const float*)d_in[1];
  float* out = (float*)d_out;
  displace_gauss_kernel<<<B * C, 256>>>(x, offset, out);
}

// round 2
// speedup vs baseline: 1.9750x; 1.9750x over previous
#include <cuda_runtime.h>

namespace {
constexpr int H = 64, W = 64;
constexpr int C = 384;   // 48 positions * 8 channels
constexpr int B = 32;
constexpr int AP = 72;   // smem row pitch (floats), 288B -> 16B-aligned rows
constexpr int AR = 68;   // logical rows/cols of padded+displaced tile
}

__global__ __launch_bounds__(256) void displace_gauss_kernel(
    const float* __restrict__ x, const float* __restrict__ offset,
    float* __restrict__ out) {
  __shared__ __align__(16) float A[AR * AP];
  __shared__ float swx[5], swy[5];

  const int plane = blockIdx.x;         // b*C + c
  const int c = plane % C;
  const int p = c >> 3;                 // 8 channels per position
  const int tid = threadIdx.x;

  // --- every thread computes integer offset itself (broadcast loads) ---
  const float ox = __ldg(&offset[2 * p + 0]);
  const float oy = __ldg(&offset[2 * p + 1]);
  const float rx = rintf(ox), ry = rintf(oy);   // matches jnp.round
  const int dx = (int)rx;
  const int dy = (int)ry;

  // --- Gaussian weights: lane 0 does x-axis, lane 1 does y-axis ---
  if (tid < 2) {
    const float sub = (tid == 0) ? (ox - rx) : (oy - ry);
    float e[5], s = 0.f;
#pragma unroll
    for (int j = 0; j < 5; j++) {
      float d = (float)(j - 2) + sub;
      e[j] = expf(-d * d * 2.0f);       // 1/(2*sigma^2) = 2 for sigma=0.5
      s += e[j];
    }
    const float inv = 1.0f / s;         // 2D norm = product of 1D norms
    float* w = (tid == 0) ? swx : swy;
#pragma unroll
    for (int j = 0; j < 5; j++) w[j] = e[j] * inv;
  }

  // --- zero the 2-wide halo (always zero: px/py out of [0,64) there) ---
  if (tid < AR) {
    A[0 * AP + tid] = 0.f;  A[1 * AP + tid] = 0.f;
    A[66 * AP + tid] = 0.f; A[67 * AP + tid] = 0.f;
    float* row = &A[tid * AP];
    row[0] = 0.f; row[1] = 0.f; row[66] = 0.f; row[67] = 0.f;
  }

  // --- fill 64x64 interior: fixed 2D decomposition, no div/mod ---
  const float* __restrict__ src = x + (size_t)plane * (H * W);
  const int tx = tid & 63;              // column 0..63
  const int ty = tid >> 6;              // row phase 0..3
  const int sx = tx - dx;
  const bool sxok = (unsigned)sx < (unsigned)W;   // once per thread
  float* __restrict__ dstA = &A[(2 + ty) * AP + 2 + tx];
#pragma unroll
  for (int i = 0; i < 16; i++) {
    const int py = ty + i * 4;
    const int sy = py - dy;
    float v = 0.f;
    if (sxok && (unsigned)sy < (unsigned)H) v = __ldg(&src[sy * W + sx]);
    dstA[i * 4 * AP] = v;
  }
  __syncthreads();                      // single barrier

  const float wx0 = swx[0], wx1 = swx[1], wx2 = swx[2], wx3 = swx[3], wx4 = swx[4];
  float wy[5];
#pragma unroll
  for (int i = 0; i < 5; i++) wy[i] = swy[i];

  // --- separable conv, 4x4 outputs per thread, register row-sliding ---
  const int txi = tid & 15;             // 16 x-tiles of width 4
  const int tyi = tid >> 4;             // 16 y-tiles of height 4
  const int x0 = txi * 4;
  const int y0 = tyi * 4;

  float acc[4][4];
#pragma unroll
  for (int o = 0; o < 4; o++)
#pragma unroll
    for (int u = 0; u < 4; u++) acc[o][u] = 0.f;

#pragma unroll
  for (int r = 0; r < 8; r++) {         // 8 h-rows feed 4 output rows
    const float* row = &A[(y0 + r) * AP + x0];
    float4 a0 = *reinterpret_cast<const float4*>(row);
    float4 a1 = *reinterpret_cast<const float4*>(row + 4);
    float a[8] = {a0.x, a0.y, a0.z, a0.w, a1.x, a1.y, a1.z, a1.w};
    float h[4];
#pragma unroll
    for (int u = 0; u < 4; u++)
      h[u] = wx0 * a[u] + wx1 * a[u + 1] + wx2 * a[u + 2]
           + wx3 * a[u + 3] + wx4 * a[u + 4];
#pragma unroll
    for (int o = 0; o < 4; o++) {
      int i = r - o;                    // compile-time pruned
      if (i >= 0 && i < 5) {
        float wv = wy[i];
#pragma unroll
        for (int u = 0; u < 4; u++) acc[o][u] += wv * h[u];
      }
    }
  }

  float* __restrict__ dst = out + (size_t)plane * (H * W);
#pragma unroll
  for (int o = 0; o < 4; o++) {
    float4 v = make_float4(acc[o][0], acc[o][1], acc[o][2], acc[o][3]);
    *reinterpret_cast<float4*>(&dst[(y0 + o) * W + x0]) = v;
  }
}

extern "C" void kernel_launch(void* const* d_in, const int* in_sizes, int n_in,
                              void* d_out, int out_size) {
  const float* x = (const float*)d_in[0];
  const float* offset = (const float*)d_in[1];
  float* out = (float*)d_out;
  displace_gauss_kernel<<<B * C, 256>>>(x, offset, out);
}

// round 3
// speedup vs baseline: 2.0582x; 1.0421x over previous
#include <cuda_runtime.h>

namespace {
constexpr int H = 64, W = 64;
constexpr int C = 384;   // 48 positions * 8 channels
constexpr int B = 32;
constexpr int AP = 72;   // smem row pitch (floats), 288B -> 16B-aligned rows
constexpr int AR = 68;   // logical rows/cols of padded+displaced tile
}

__global__ __launch_bounds__(256) void displace_gauss_kernel(
    const float* __restrict__ x, const float* __restrict__ offset,
    float* __restrict__ out) {
  __shared__ __align__(16) float A[2][AR * AP];
  __shared__ float swx[5], swy[5];

  const int plane0 = blockIdx.x * 2;    // two planes, same position group
  const int c = plane0 % C;
  const int p = c >> 3;                 // c even => c and c+1 share p
  const int tid = threadIdx.x;
  const int pl = tid >> 7;              // which plane this thread works on
  const int t2 = tid & 127;

  // --- every thread computes integer offset itself (broadcast loads) ---
  const float ox = __ldg(&offset[2 * p + 0]);
  const float oy = __ldg(&offset[2 * p + 1]);
  const float rx = rintf(ox), ry = rintf(oy);   // matches jnp.round
  const int dx = (int)rx;
  const int dy = (int)ry;

  // --- Gaussian weights: lane 0 does x-axis, lane 1 does y-axis ---
  if (tid < 2) {
    const float sub = (tid == 0) ? (ox - rx) : (oy - ry);
    float e[5], s = 0.f;
#pragma unroll
    for (int j = 0; j < 5; j++) {
      float d = (float)(j - 2) + sub;
      e[j] = expf(-d * d * 2.0f);       // 1/(2*sigma^2) = 2 for sigma=0.5
      s += e[j];
    }
    const float inv = 1.0f / s;         // 2D norm = product of 1D norms
    float* w = (tid == 0) ? swx : swy;
#pragma unroll
    for (int j = 0; j < 5; j++) w[j] = e[j] * inv;
  }

  // --- zero the 2-wide halo of both planes (always zero) ---
  if (t2 < AR) {
    float* Apl = A[pl];
    Apl[0 * AP + t2] = 0.f;  Apl[1 * AP + t2] = 0.f;
    Apl[66 * AP + t2] = 0.f; Apl[67 * AP + t2] = 0.f;
    float* row = &Apl[t2 * AP];
    row[0] = 0.f; row[1] = 0.f; row[66] = 0.f; row[67] = 0.f;
  }

  // --- fill 64x64 interior of this thread's plane (no div/mod) ---
  const float* __restrict__ src = x + (size_t)(plane0 + pl) * (H * W);
  const int tx = t2 & 63;               // column 0..63
  const int typh = t2 >> 6;             // row phase 0..1
  const int sx = tx - dx;
  const bool sxok = (unsigned)sx < (unsigned)W;   // once per thread
  float* __restrict__ dstA = &A[pl][(2 + typh) * AP + 2 + tx];
#pragma unroll
  for (int i = 0; i < 32; i++) {
    const int py = typh + i * 2;
    const int sy = py - dy;
    float v = 0.f;
    if (sxok && (unsigned)sy < (unsigned)H) v = __ldg(&src[sy * W + sx]);
    dstA[i * 2 * AP] = v;
  }
  __syncthreads();                      // single barrier

  const float wx0 = swx[0], wx1 = swx[1], wx2 = swx[2], wx3 = swx[3], wx4 = swx[4];
  float wy[5];
#pragma unroll
  for (int i = 0; i < 5; i++) wy[i] = swy[i];

  // --- separable conv, 4 wide x 8 tall outputs per thread ---
  const int txi = t2 & 15;              // 16 x-tiles of width 4
  const int tyi = t2 >> 4;              // 8 y-tiles of height 8
  const int x0 = txi * 4;
  const int y0 = tyi * 8;
  const float* __restrict__ Apl = A[pl];

  float acc[8][4];
#pragma unroll
  for (int o = 0; o < 8; o++)
#pragma unroll
    for (int u = 0; u < 4; u++) acc[o][u] = 0.f;

#pragma unroll
  for (int r = 0; r < 12; r++) {        // 12 h-rows feed 8 output rows
    const float* row = &Apl[(y0 + r) * AP + x0];
    float4 a0 = *reinterpret_cast<const float4*>(row);
    float4 a1 = *reinterpret_cast<const float4*>(row + 4);
    float a[8] = {a0.x, a0.y, a0.z, a0.w, a1.x, a1.y, a1.z, a1.w};
    float h[4];
#pragma unroll
    for (int u = 0; u < 4; u++)
      h[u] = wx0 * a[u] + wx1 * a[u + 1] + wx2 * a[u + 2]
           + wx3 * a[u + 3] + wx4 * a[u + 4];
#pragma unroll
    for (int o = 0; o < 8; o++) {
      int i = r - o;                    // compile-time pruned
      if (i >= 0 && i < 5) {
        float wv = wy[i];
#pragma unroll
        for (int u = 0; u < 4; u++) acc[o][u] += wv * h[u];
      }
    }
  }

  float* __restrict__ dst = out + (size_t)(plane0 + pl) * (H * W);
#pragma unroll
  for (int o = 0; o < 8; o++) {
    float4 v = make_float4(acc[o][0], acc[o][1], acc[o][2], acc[o][3]);
    *reinterpret_cast<float4*>(&dst[(y0 + o) * W + x0]) = v;
  }
}

extern "C" void kernel_launch(void* const* d_in, const int* in_sizes, int n_in,
                              void* d_out, int out_size) {
  const float* x = (const float*)d_in[0];
  const float* offset = (const float*)d_in[1];
  float* out = (float*)d_out;
  displace_gauss_kernel<<<(B * C) / 2, 256>>>(x, offset, out);
}

// round 4
// speedup vs baseline: 2.1205x; 1.0303x over previous
#include <cuda_runtime.h>

namespace {
constexpr int H = 64, W = 64;
constexpr int C = 384;   // 48 positions * 8 channels
constexpr int B = 32;
constexpr int AP = 72;   // smem row pitch (floats), 288B -> 16B-aligned rows
constexpr int AR = 68;   // logical rows/cols of padded+displaced tile
}

__global__ __launch_bounds__(256) void displace_gauss_kernel(
    const float* __restrict__ x, const float* __restrict__ offset,
    float* __restrict__ out) {
  __shared__ __align__(16) float A[2][AR * AP];
  __shared__ float swx[5], swy[5];

  const int plane0 = blockIdx.x * 2;    // two planes, same position group
  const int c = plane0 % C;
  const int p = c >> 3;                 // c even => c and c+1 share p
  const int tid = threadIdx.x;
  const int pl = tid >> 7;              // which plane this thread works on
  const int t2 = tid & 127;

  // --- every thread computes integer offset itself (broadcast loads) ---
  const float ox = __ldg(&offset[2 * p + 0]);
  const float oy = __ldg(&offset[2 * p + 1]);
  const float rx = rintf(ox), ry = rintf(oy);   // matches jnp.round
  const int dx = (int)rx;
  const int dy = (int)ry;

  // --- Gaussian weights: lane 0 does x-axis, lane 1 does y-axis ---
  if (tid < 2) {
    const float sub = (tid == 0) ? (ox - rx) : (oy - ry);
    float e[5], s = 0.f;
#pragma unroll
    for (int j = 0; j < 5; j++) {
      float d = (float)(j - 2) + sub;
      e[j] = expf(-d * d * 2.0f);       // 1/(2*sigma^2) = 2 for sigma=0.5
      s += e[j];
    }
    const float inv = 1.0f / s;         // 2D norm = product of 1D norms
    float* w = (tid == 0) ? swx : swy;
#pragma unroll
    for (int j = 0; j < 5; j++) w[j] = e[j] * inv;
  }

  // --- zero the 2-wide halo of both planes (always zero) ---
  if (t2 < AR) {
    float* Apl = A[pl];
    Apl[0 * AP + t2] = 0.f;  Apl[1 * AP + t2] = 0.f;
    Apl[66 * AP + t2] = 0.f; Apl[67 * AP + t2] = 0.f;
    float* row = &Apl[t2 * AP];
    row[0] = 0.f; row[1] = 0.f; row[66] = 0.f; row[67] = 0.f;
  }

  // --- fill 64x64 interior of this thread's plane (no div/mod) ---
  const float* __restrict__ src = x + (size_t)(plane0 + pl) * (H * W);
  const int tx = t2 & 63;               // column 0..63
  const int typh = t2 >> 6;             // row phase 0..1
  const int sx = tx - dx;
  const bool sxok = (unsigned)sx < (unsigned)W;   // once per thread
  float* __restrict__ dstA = &A[pl][(2 + typh) * AP + 2 + tx];
#pragma unroll
  for (int i = 0; i < 32; i++) {
    const int py = typh + i * 2;
    const int sy = py - dy;
    float v = 0.f;
    if (sxok && (unsigned)sy < (unsigned)H) v = __ldg(&src[sy * W + sx]);
    dstA[i * 2 * AP] = v;
  }
  __syncthreads();                      // single barrier

  // --- per-thread output tile coordinates ---
  const int txi = t2 & 15;              // 16 x-tiles of width 4
  const int tyi = t2 >> 4;              // 8 y-tiles of height 8
  const int x0 = txi * 4;
  const int y0 = tyi * 8;
  float* __restrict__ dst = out + (size_t)(plane0 + pl) * (H * W);

  // --- liveness: does this tile's input window touch any valid pixel? ---
  // valid displaced cols: [max(0,dx), min(W-1, W-1+dx)]; rows analogous.
  // tile input window: cols [x0-2, x0+5], rows [y0-2, y0+9].
  {
    const int cx0 = dx > 0 ? dx : 0;
    const int cx1 = dx < 0 ? (W - 1 + dx) : (W - 1);
    const int cy0 = dy > 0 ? dy : 0;
    const int cy1 = dy < 0 ? (H - 1 + dy) : (H - 1);
    const bool live = (x0 + 5 >= cx0) & (x0 - 2 <= cx1) &
                      (y0 + 9 >= cy0) & (y0 - 2 <= cy1);
    if (!live) {                        // entire tile is exactly zero
      const float4 z = make_float4(0.f, 0.f, 0.f, 0.f);
#pragma unroll
      for (int o = 0; o < 8; o++)
        *reinterpret_cast<float4*>(&dst[(y0 + o) * W + x0]) = z;
      return;                           // no more barriers follow
    }
  }

  const float wx0 = swx[0], wx1 = swx[1], wx2 = swx[2], wx3 = swx[3], wx4 = swx[4];
  float wy[5];
#pragma unroll
  for (int i = 0; i < 5; i++) wy[i] = swy[i];

  // --- separable conv, 4 wide x 8 tall outputs per thread ---
  const float* __restrict__ Apl = A[pl];
  float acc[8][4];
#pragma unroll
  for (int o = 0; o < 8; o++)
#pragma unroll
    for (int u = 0; u < 4; u++) acc[o][u] = 0.f;

#pragma unroll
  for (int r = 0; r < 12; r++) {        // 12 h-rows feed 8 output rows
    const float* row = &Apl[(y0 + r) * AP + x0];
    float4 a0 = *reinterpret_cast<const float4*>(row);
    float4 a1 = *reinterpret_cast<const float4*>(row + 4);
    float a[8] = {a0.x, a0.y, a0.z, a0.w, a1.x, a1.y, a1.z, a1.w};
    float h[4];
#pragma unroll
    for (int u = 0; u < 4; u++)
      h[u] = wx0 * a[u] + wx1 * a[u + 1] + wx2 * a[u + 2]
           + wx3 * a[u + 3] + wx4 * a[u + 4];
#pragma unroll
    for (int o = 0; o < 8; o++) {
      int i = r - o;                    // compile-time pruned
      if (i >= 0 && i < 5) {
        float wv = wy[i];
#pragma unroll
        for (int u = 0; u < 4; u++) acc[o][u] += wv * h[u];
      }
    }
  }

#pragma unroll
  for (int o = 0; o < 8; o++) {
    float4 v = make_float4(acc[o][0], acc[o][1], acc[o][2], acc[o][3]);
    *reinterpret_cast<float4*>(&dst[(y0 + o) * W + x0]) = v;
  }
}

extern "C" void kernel_launch(void* const* d_in, const int* in_sizes, int n_in,
                              void* d_out, int out_size) {
  const float* x = (const float*)d_in[0];
  const float* offset = (const float*)d_in[1];
  float* out = (float*)d_out;
  displace_gauss_kernel<<<(B * C) / 2, 256>>>(x, offset, out);
}

// round 5
// speedup vs baseline: 2.1315x; 1.0052x over previous
#include <cuda_runtime.h>

namespace {
constexpr int H = 64, W = 64;
constexpr int C = 384;   // 48 positions * 8 channels
constexpr int B = 32;
constexpr int AP = 72;   // smem row pitch (floats), 288B -> 16B-aligned rows
constexpr int AR = 68;   // logical rows/cols of padded+displaced tile
}

__global__ __launch_bounds__(256, 6) void displace_gauss_kernel(
    const float* __restrict__ x, const float* __restrict__ offset,
    float* __restrict__ out) {
  __shared__ __align__(16) float A[AR * AP];
  __shared__ float swx[5], swy[5];

  const int plane = blockIdx.x;         // b*C + c
  const int c = plane % C;
  const int p = c >> 3;                 // 8 channels per position
  const int tid = threadIdx.x;

  // --- every thread computes integer offset itself (broadcast loads) ---
  const float ox = __ldg(&offset[2 * p + 0]);
  const float oy = __ldg(&offset[2 * p + 1]);
  const float rx = rintf(ox), ry = rintf(oy);   // matches jnp.round
  const int dx = (int)rx;
  const int dy = (int)ry;

  // --- Gaussian weights: lane 0 does x-axis, lane 1 does y-axis ---
  if (tid < 2) {
    const float sub = (tid == 0) ? (ox - rx) : (oy - ry);
    float e[5], s = 0.f;
#pragma unroll
    for (int j = 0; j < 5; j++) {
      float d = (float)(j - 2) + sub;
      e[j] = expf(-d * d * 2.0f);       // 1/(2*sigma^2) = 2 for sigma=0.5
      s += e[j];
    }
    const float inv = 1.0f / s;         // 2D norm = product of 1D norms
    float* w = (tid == 0) ? swx : swy;
#pragma unroll
    for (int j = 0; j < 5; j++) w[j] = e[j] * inv;
  }

  // --- zero the 2-wide halo (always zero: px/py out of [0,64) there) ---
  if (tid < AR) {
    A[0 * AP + tid] = 0.f;  A[1 * AP + tid] = 0.f;
    A[66 * AP + tid] = 0.f; A[67 * AP + tid] = 0.f;
    float* row = &A[tid * AP];
    row[0] = 0.f; row[1] = 0.f; row[66] = 0.f; row[67] = 0.f;
  }

  // --- fill 64x64 interior ---
  const float* __restrict__ src = x + (size_t)plane * (H * W);
  const int fx = tid & 15;              // float4 column index 0..15
  const int fy = tid >> 4;              // row 0..15 (4 strided passes)
  const int px = fx * 4;
  float* __restrict__ dstA = &A[(2 + fy) * AP + 2 + px];

  if ((dx & 3) == 0) {
    // vector path: displaced float4 stays aligned & validity is all-or-none
    const int sx = px - dx;             // multiple of 4
    const bool sxok = (unsigned)sx < (unsigned)W;
#pragma unroll
    for (int i = 0; i < 4; i++) {
      const int sy = fy + i * 16 - dy;
      float4 v = make_float4(0.f, 0.f, 0.f, 0.f);
      if (sxok && (unsigned)sy < (unsigned)H)
        v = __ldcs(reinterpret_cast<const float4*>(&src[sy * W + sx]));
      float* d = dstA + i * 16 * AP;    // col 2+4k: 8B-aligned -> STS.64 x2
      *reinterpret_cast<float2*>(d + 0) = make_float2(v.x, v.y);
      *reinterpret_cast<float2*>(d + 2) = make_float2(v.z, v.w);
    }
  } else {
    // generic scalar path (not taken for this problem's offset grid)
#pragma unroll
    for (int i = 0; i < 4; i++) {
      const int sy = fy + i * 16 - dy;
      const bool syok = (unsigned)sy < (unsigned)H;
#pragma unroll
      for (int u = 0; u < 4; u++) {
        const int sx = px + u - dx;
        float v = 0.f;
        if (syok && (unsigned)sx < (unsigned)W) v = __ldcs(&src[sy * W + sx]);
        dstA[i * 16 * AP + u] = v;
      }
    }
  }
  __syncthreads();                      // single barrier

  // --- per-thread output tile coordinates (4 wide x 4 tall) ---
  const int txi = tid & 15;             // 16 x-tiles of width 4
  const int tyi = tid >> 4;             // 16 y-tiles of height 4
  const int x0 = txi * 4;
  const int y0 = tyi * 4;
  float* __restrict__ dst = out + (size_t)plane * (H * W);

  // --- liveness: does this tile's input window touch any valid pixel? ---
  // valid displaced cols: [max(0,dx), min(W-1, W-1+dx)]; rows analogous.
  // tile input window: cols [x0-2, x0+5], rows [y0-2, y0+5].
  {
    const int cx0 = dx > 0 ? dx : 0;
    const int cx1 = dx < 0 ? (W - 1 + dx) : (W - 1);
    const int cy0 = dy > 0 ? dy : 0;
    const int cy1 = dy < 0 ? (H - 1 + dy) : (H - 1);
    const bool live = (x0 + 5 >= cx0) & (x0 - 2 <= cx1) &
                      (y0 + 5 >= cy0) & (y0 - 2 <= cy1);
    if (!live) {                        // entire tile is exactly zero
      const float4 z = make_float4(0.f, 0.f, 0.f, 0.f);
#pragma unroll
      for (int o = 0; o < 4; o++)
        __stcs(reinterpret_cast<float4*>(&dst[(y0 + o) * W + x0]), z);
      return;                           // no more barriers follow
    }
  }

  const float wx0 = swx[0], wx1 = swx[1], wx2 = swx[2], wx3 = swx[3], wx4 = swx[4];
  float wy[5];
#pragma unroll
  for (int i = 0; i < 5; i++) wy[i] = swy[i];

  // --- separable conv, 4x4 outputs per thread, register row-sliding ---
  float acc[4][4];
#pragma unroll
  for (int o = 0; o < 4; o++)
#pragma unroll
    for (int u = 0; u < 4; u++) acc[o][u] = 0.f;

#pragma unroll
  for (int r = 0; r < 8; r++) {         // 8 h-rows feed 4 output rows
    const float* row = &A[(y0 + r) * AP + x0];
    float4 a0 = *reinterpret_cast<const float4*>(row);
    float4 a1 = *reinterpret_cast<const float4*>(row + 4);
    float a[8] = {a0.x, a0.y, a0.z, a0.w, a1.x, a1.y, a1.z, a1.w};
    float h[4];
#pragma unroll
    for (int u = 0; u < 4; u++)
      h[u] = wx0 * a[u] + wx1 * a[u + 1] + wx2 * a[u + 2]
           + wx3 * a[u + 3] + wx4 * a[u + 4];
#pragma unroll
    for (int o = 0; o < 4; o++) {
      int i = r - o;                    // compile-time pruned
      if (i >= 0 && i < 5) {
        float wv = wy[i];
#pragma unroll
        for (int u = 0; u < 4; u++) acc[o][u] += wv * h[u];
      }
    }
  }

#pragma unroll
  for (int o = 0; o < 4; o++) {
    float4 v = make_float4(acc[o][0], acc[o][1], acc[o][2], acc[o][3]);
    __stcs(reinterpret_cast<float4*>(&dst[(y0 + o) * W + x0]), v);
  }
}

extern "C" void kernel_launch(void* const* d_in, const int* in_sizes, int n_in,
                              void* d_out, int out_size) {
  const float* x = (const float*)d_in[0];
  const float* offset = (const float*)d_in[1];
  float* out = (float*)d_out;
  displace_gauss_kernel<<<B * C, 256>>>(x, offset, out);
}